// round 3
// baseline (speedup 1.0000x reference)
#include <cuda_runtime.h>
#include <math.h>

#define HWD 96
#define NB 8

// ---------------- static device scratch (no allocations allowed) ----------------
__device__ float g_cat[(size_t)NB * 320 * HWD * HWD];   // upsample+concat input (94.4 MB)
__device__ float g_h1[(size_t)NB * 128 * HWD * HWD];    // branch intermediate 1
__device__ float g_h2[(size_t)NB * 128 * HWD * HWD];    // branch intermediate 2
__device__ float g_ww2[(size_t)NB * 576 * HWD * HWD];   // ww2 conv output (before global max)
__device__ float g_gmax[NB * 576];

// ---------------- upsample(bilinear x4, align-corners) + channel concat ----------------
__global__ void upcat_kernel(const float* __restrict__ z2, const float* __restrict__ y1,
                             float* __restrict__ cat) {
    long idx = (long)blockIdx.x * blockDim.x + threadIdx.x;
    const long total = (long)NB * 320 * HWD * HWD;
    if (idx >= total) return;
    int X = (int)(idx % HWD);
    long t = idx / HWD;
    int Y = (int)(t % HWD); t /= HWD;
    int c = (int)(t % 320);
    int b = (int)(t / 320);
    float v;
    if (c < 128) {
        const float S = 23.0f / 95.0f;   // (h-1)/(H-1)
        float fy = Y * S, fx = X * S;
        int y0 = (int)fy, x0 = (int)fx;  // floor (nonneg)
        int y1i = min(y0 + 1, 23), x1i = min(x0 + 1, 23);
        float wy = fy - (float)y0, wx = fx - (float)x0;
        const float* p = z2 + ((size_t)(b * 128 + c) * 24) * 24;
        float a  = p[y0  * 24 + x0 ];
        float bq = p[y0  * 24 + x1i];
        float cq = p[y1i * 24 + x0 ];
        float dq = p[y1i * 24 + x1i];
        float top = a  * (1.f - wx) + bq * wx;
        float bot = cq * (1.f - wx) + dq * wx;
        v = top * (1.f - wy) + bot * wy;
    } else {
        v = y1[((size_t)(b * 192 + (c - 128)) * HWD + Y) * HWD + X];
    }
    cat[idx] = v;
}

// ---------------- direct 5x5 conv, pad=2, register-staged pipeline ----------------
// Block: 32(x) x 8(y) spatial x 32 output channels; 256 threads.
// Warp g owns oc [oc0+4g, oc0+4g+4); thread s: row (s>>2), x-base (s&3)*8,
// i.e. 4 oc x 8 x-positions = 32 accumulators.
// Gmem loads for iteration i+1 are staged into registers (pin/pw) before the
// compute of iteration i, hiding L2/DRAM latency behind 3200 cyc of FFMA.
// ACT: 0=none, 1=relu, 2=lrelu(0.01)
template <int CIN, int COUT, int ACT>
__global__ void __launch_bounds__(256)
conv5_kernel(const float* __restrict__ in, const float* __restrict__ w,
             const float* __restrict__ bias, float* __restrict__ out) {
    constexpr int TW = 32, TH = 8, OCB = 32, CS = 4;
    constexpr int IW = TW + 5;                 // pad to 37 -> conflict-free inner loads
    constexpr int IN_TOT = CS * (TH + 4) * (TW + 4);   // 1728
    constexpr int W_TOT  = CS * 25 * OCB;              // 3200
    constexpr int IN_PT  = (IN_TOT + 255) / 256;       // 7
    constexpr int W_PT   = (W_TOT + 255) / 256;        // 13
    __shared__ __align__(16) float ism[CS][TH + 4][IW];
    __shared__ __align__(16) float wsm[CS][25][OCB];

    const int tx0 = blockIdx.x * TW;
    const int ty0 = blockIdx.y * TH;
    const int ocTiles = COUT / OCB;
    const int b   = (int)blockIdx.z / ocTiles;
    const int oc0 = ((int)blockIdx.z % ocTiles) * OCB;

    const int tid = threadIdx.x;
    const int g = tid >> 5;          // warp id = oc group
    const int s = tid & 31;
    const int row = s >> 2;          // 0..7
    const int xb  = (s & 3) * 8;     // 0,8,16,24

    float acc[4][8];
#pragma unroll
    for (int j = 0; j < 4; j++)
#pragma unroll
        for (int i = 0; i < 8; i++) acc[j][i] = 0.f;

    const float* inB = in + (size_t)b * CIN * HWD * HWD;

    float pin[IN_PT];
    float pw[W_PT];

    // stage loader: gmem -> registers for channel block starting at c0
    auto stage = [&](int c0) {
#pragma unroll
        for (int k = 0; k < IN_PT; k++) {
            int idx = tid + k * 256;
            float v = 0.f;
            if (idx < IN_TOT) {
                int c  = idx / ((TH + 4) * (TW + 4));
                int r  = idx % ((TH + 4) * (TW + 4));
                int iy = r / (TW + 4);
                int ix = r % (TW + 4);
                int gy = ty0 + iy - 2;
                int gx = tx0 + ix - 2;
                if ((unsigned)gy < HWD && (unsigned)gx < HWD)
                    v = __ldg(&inB[((size_t)(c0 + c) * HWD + gy) * HWD + gx]);
            }
            pin[k] = v;
        }
#pragma unroll
        for (int k = 0; k < W_PT; k++) {
            int idx = tid + k * 256;
            float v = 0.f;
            if (idx < W_TOT) {
                int oc   = idx & 31;
                int rest = idx >> 5;
                int tap  = rest % 25;
                int c    = rest / 25;
                v = __ldg(&w[((size_t)(oc0 + oc) * CIN + (c0 + c)) * 25 + tap]);
            }
            pw[k] = v;
        }
    };

    // commit loader: registers -> smem
    auto commit = [&]() {
#pragma unroll
        for (int k = 0; k < IN_PT; k++) {
            int idx = tid + k * 256;
            if (idx < IN_TOT) {
                int c  = idx / ((TH + 4) * (TW + 4));
                int r  = idx % ((TH + 4) * (TW + 4));
                int iy = r / (TW + 4);
                int ix = r % (TW + 4);
                ism[c][iy][ix] = pin[k];
            }
        }
#pragma unroll
        for (int k = 0; k < W_PT; k++) {
            int idx = tid + k * 256;
            if (idx < W_TOT) {
                int oc   = idx & 31;
                int rest = idx >> 5;
                int tap  = rest % 25;
                int c    = rest / 25;
                wsm[c][tap][oc] = pw[k];
            }
        }
    };

    stage(0);
    for (int c0 = 0; c0 < CIN; c0 += CS) {
        __syncthreads();     // WAR: compute of previous iter done before overwrite
        commit();
        __syncthreads();
        if (c0 + CS < CIN) stage(c0 + CS);   // LDGs overlap the FFMA block below

#pragma unroll 1
        for (int c = 0; c < CS; c++) {
#pragma unroll 1
            for (int ky = 0; ky < 5; ky++) {
                // register-cache the 12-float input span (conflict-free LDS)
                float vin[12];
                const float* ip = &ism[c][row + ky][xb];
#pragma unroll
                for (int i = 0; i < 12; i++) vin[i] = ip[i];
                // weights: 4 consecutive oc as float4 (16B aligned, warp-uniform)
                const float4* wp4 = reinterpret_cast<const float4*>(&wsm[c][ky * 5][g * 4]);
#pragma unroll
                for (int kx = 0; kx < 5; kx++) {
                    float4 wq = wp4[kx * (OCB / 4)];
#pragma unroll
                    for (int i = 0; i < 8; i++) {
                        float v = vin[kx + i];
                        acc[0][i] = fmaf(v, wq.x, acc[0][i]);
                        acc[1][i] = fmaf(v, wq.y, acc[1][i]);
                        acc[2][i] = fmaf(v, wq.z, acc[2][i]);
                        acc[3][i] = fmaf(v, wq.w, acc[3][i]);
                    }
                }
            }
        }
    }

    // epilogue: bias + activation + vectorized store
    const int oy = ty0 + row;
#pragma unroll
    for (int j = 0; j < 4; j++) {
        int oc = oc0 + g * 4 + j;
        float bv = bias[oc];
        float r[8];
#pragma unroll
        for (int i = 0; i < 8; i++) {
            float x = acc[j][i] + bv;
            if (ACT == 1) x = fmaxf(x, 0.f);
            if (ACT == 2) x = (x >= 0.f) ? x : 0.01f * x;
            r[i] = x;
        }
        float4* op = reinterpret_cast<float4*>(
            out + (((size_t)b * COUT + oc) * HWD + oy) * HWD + tx0 + xb);
        op[0] = make_float4(r[0], r[1], r[2], r[3]);
        op[1] = make_float4(r[4], r[5], r[6], r[7]);
    }
}

// ---------------- global max over HxW per (b, oc) ----------------
__global__ void maxred_kernel(const float* __restrict__ x, float* __restrict__ gmax) {
    __shared__ float sm[256];
    int bc = blockIdx.x;  // b*576 + oc
    const float* p = x + (size_t)bc * HWD * HWD;
    float m = -3.402823466e38f;
    for (int i = threadIdx.x; i < HWD * HWD; i += 256) m = fmaxf(m, p[i]);
    sm[threadIdx.x] = m;
    __syncthreads();
    for (int st = 128; st > 0; st >>= 1) {
        if (threadIdx.x < st) sm[threadIdx.x] = fmaxf(sm[threadIdx.x], sm[threadIdx.x + st]);
        __syncthreads();
    }
    if (threadIdx.x == 0) gmax[bc] = sm[0];
}

// ---------------- lrelu -> 1x1 conv 576->576 -> grouped softmax (K=3 over M=192) ----------------
__global__ void weights_kernel(const float* __restrict__ gmax, const float* __restrict__ ww3,
                               const float* __restrict__ bw3, float* __restrict__ outw) {
    __shared__ float gsm[576];
    __shared__ float osm[576];
    int b = blockIdx.x;
    int t = threadIdx.x;  // 576 threads
    float x = gmax[b * 576 + t];
    gsm[t] = (x >= 0.f) ? x : 0.01f * x;
    __syncthreads();
    float accv = bw3[t];
    const float* wr = ww3 + (size_t)t * 576;
    for (int i = 0; i < 576; i++) accv = fmaf(wr[i], gsm[i], accv);
    osm[t] = accv;
    __syncthreads();
    if (t < 192) {
        float a = osm[t], bq = osm[192 + t], cq = osm[384 + t];
        float mx = fmaxf(a, fmaxf(bq, cq));
        float ea = expf(a - mx), eb = expf(bq - mx), ec = expf(cq - mx);
        float inv = 1.f / (ea + eb + ec);
        outw[b * 576 + t]       = ea * inv;
        outw[b * 576 + 192 + t] = eb * inv;
        outw[b * 576 + 384 + t] = ec * inv;
    }
}

// ---------------- launch ----------------
extern "C" void kernel_launch(void* const* d_in, const int* in_sizes, int n_in,
                              void* d_out, int out_size) {
    const float* z2  = (const float*)d_in[0];
    const float* y1  = (const float*)d_in[1];
    const float* ws1 = (const float*)d_in[2];  const float* bs1 = (const float*)d_in[3];
    const float* ws2 = (const float*)d_in[4];  const float* bs2 = (const float*)d_in[5];
    const float* ws3 = (const float*)d_in[6];  const float* bs3 = (const float*)d_in[7];
    const float* wm1 = (const float*)d_in[8];  const float* bm1 = (const float*)d_in[9];
    const float* wm2 = (const float*)d_in[10]; const float* bm2 = (const float*)d_in[11];
    const float* wm3 = (const float*)d_in[12]; const float* bm3 = (const float*)d_in[13];
    const float* ww1 = (const float*)d_in[14]; const float* bw1 = (const float*)d_in[15];
    const float* ww2 = (const float*)d_in[16]; const float* bw2 = (const float*)d_in[17];
    const float* ww3 = (const float*)d_in[18]; const float* bw3 = (const float*)d_in[19];
    float* out = (float*)d_out;

    float *cat, *h1, *h2, *ww2o, *gmax;
    cudaGetSymbolAddress((void**)&cat,  g_cat);
    cudaGetSymbolAddress((void**)&h1,   g_h1);
    cudaGetSymbolAddress((void**)&h2,   g_h2);
    cudaGetSymbolAddress((void**)&ww2o, g_ww2);
    cudaGetSymbolAddress((void**)&gmax, g_gmax);

    const size_t SIG_OFF = 0;
    const size_t MEA_OFF = (size_t)NB * 576 * HWD * HWD;       // 42,467,328
    const size_t WGT_OFF = 2 * MEA_OFF;                        // 84,934,656

    // upsample + concat
    {
        long total = (long)NB * 320 * HWD * HWD;
        int blocks = (int)((total + 255) / 256);
        upcat_kernel<<<blocks, 256>>>(z2, y1, cat);
    }

    dim3 blk(256);
    dim3 grid128(HWD / 32, HWD / 8, NB * (128 / 32));
    dim3 grid576(HWD / 32, HWD / 8, NB * (576 / 32));

    // sigma branch
    conv5_kernel<320, 128, 1><<<grid128, blk>>>(cat, ws1, bs1, h1);
    conv5_kernel<128, 128, 1><<<grid128, blk>>>(h1, ws2, bs2, h2);
    conv5_kernel<128, 576, 1><<<grid576, blk>>>(h2, ws3, bs3, out + SIG_OFF);

    // means branch
    conv5_kernel<320, 128, 2><<<grid128, blk>>>(cat, wm1, bm1, h1);
    conv5_kernel<128, 128, 2><<<grid128, blk>>>(h1, wm2, bm2, h2);
    conv5_kernel<128, 576, 0><<<grid576, blk>>>(h2, wm3, bm3, out + MEA_OFF);

    // weights branch
    conv5_kernel<320, 128, 2><<<grid128, blk>>>(cat, ww1, bw1, h1);
    conv5_kernel<128, 576, 0><<<grid576, blk>>>(h1, ww2, bw2, ww2o);
    maxred_kernel<<<NB * 576, 256>>>(ww2o, gmax);
    weights_kernel<<<NB, 576>>>(gmax, ww3, bw3, out + WGT_OFF);
}

// round 7
// speedup vs baseline: 3.7550x; 3.7550x over previous
#include <cuda_runtime.h>
#include <cstdint>
#include <math.h>

#define HWD 96
#define NB 8

__device__ float g_cat[(size_t)NB*320*HWD*HWD];
__device__ float g_h1[(size_t)NB*128*HWD*HWD];
__device__ float g_h2[(size_t)NB*128*HWD*HWD];
__device__ float g_ww2[(size_t)NB*576*HWD*HWD];
__device__ float g_gmax[NB*576];
__device__ float g_wt[10035200];   // frag-ordered, tf32-rounded weights

// ---------- helpers ----------
__device__ __forceinline__ float to_tf32(float x){ float r; asm("cvt.rna.tf32.f32 %0,%1;":"=f"(r):"f"(x)); return r; }

#define CPA8(d,s)   asm volatile("cp.async.ca.shared.global [%0],[%1],8;"::"r"(d),"l"(s):"memory")
#define CPA16(d,s)  asm volatile("cp.async.ca.shared.global [%0],[%1],16;"::"r"(d),"l"(s):"memory")
#define CP_COMMIT() asm volatile("cp.async.commit_group;":::"memory")
#define CP_WAITG0() asm volatile("cp.async.wait_group 0;":::"memory")
#define CP_WAITG1() asm volatile("cp.async.wait_group 1;":::"memory")

__device__ __forceinline__ uint32_t smem_u32(const void* p){
    uint32_t a; asm("{ .reg .u64 t; cvta.to.shared.u64 t, %1; cvt.u32.u64 %0, t; }":"=r"(a):"l"(p)); return a;
}

// tf32 m16n8k8 mma.sync (sm_80+ portable PTX -> tensor pipe)
__device__ __forceinline__ void mma8(float* c, const uint32_t* a, uint32_t b0, uint32_t b1){
    asm volatile("mma.sync.aligned.m16n8k8.row.col.f32.tf32.tf32.f32 "
        "{%0,%1,%2,%3},{%4,%5,%6,%7},{%8,%9},{%0,%1,%2,%3};"
        : "+f"(c[0]),"+f"(c[1]),"+f"(c[2]),"+f"(c[3])
        : "r"(a[0]),"r"(a[1]),"r"(a[2]),"r"(a[3]),"r"(b0),"r"(b1));
}

// ---------- upsample+concat (tf32 rounded) ----------
__global__ void upcat_kernel(const float* __restrict__ z2, const float* __restrict__ y1, float* __restrict__ cat){
    long idx = (long)blockIdx.x*blockDim.x + threadIdx.x;
    const long total = (long)NB*320*HWD*HWD;
    if(idx>=total) return;
    int X=(int)(idx%HWD); long t=idx/HWD; int Y=(int)(t%HWD); t/=HWD; int c=(int)(t%320); int b=(int)(t/320);
    float v;
    if(c<128){
        const float S=23.0f/95.0f; float fy=Y*S, fx=X*S;
        int y0=(int)fy, x0=(int)fx; int y1i=min(y0+1,23), x1i=min(x0+1,23);
        float wy=fy-(float)y0, wx=fx-(float)x0;
        const float* p = z2 + ((size_t)(b*128+c)*24)*24;
        float a=p[y0*24+x0], bq=p[y0*24+x1i], cq=p[y1i*24+x0], dq=p[y1i*24+x1i];
        float top=a*(1.f-wx)+bq*wx, bot=cq*(1.f-wx)+dq*wx;
        v = top*(1.f-wy)+bot*wy;
    } else v = y1[((size_t)(b*192+(c-128))*HWD+Y)*HWD+X];
    cat[idx] = to_tf32(v);
}

// ---------- weight prep: A-fragment lane order ----------
// record = ((tap*KG + kg)*MBt + mb): 32 lanes x float4:
//   oc = mb*16 + (l>>2), cin = kg*8 + (l&3)
//   {W(oc,cin), W(oc+8,cin), W(oc,cin+4), W(oc+8,cin+4)}  (tf32-rounded)
__global__ void wtrans_kernel(const float* __restrict__ w, float* __restrict__ wt,
                              int cin, int KG, int MBt){
    long idx = (long)blockIdx.x*blockDim.x + threadIdx.x;
    long total = (long)25*KG*MBt*32;
    if(idx>=total) return;
    int l = (int)(idx&31); long rec = idx>>5;
    int mb = (int)(rec % MBt); long r2 = rec / MBt;
    int kg = (int)(r2 % KG); int tap = (int)(r2 / KG);
    int oc = mb*16 + (l>>2), c = kg*8 + (l&3);
    float4 v;
    v.x = to_tf32(w[((size_t)oc*cin + c)*25 + tap]);
    v.y = to_tf32(w[((size_t)(oc+8)*cin + c)*25 + tap]);
    v.z = to_tf32(w[((size_t)oc*cin + c+4)*25 + tap]);
    v.w = to_tf32(w[((size_t)(oc+8)*cin + c+4)*25 + tap]);
    reinterpret_cast<float4*>(wt + rec*128)[l] = v;
}

// ---------- tf32 mma.sync implicit-GEMM 5x5 conv (pad=2) ----------
// Block: 128 thr = 4 warps; warp wy covers output row y0+wy, all 96 x, 64 oc.
// smem: [0..8192) weight dbuf (2 x 4KB frag records), [8192..) act 16 planes x 840 words.
// ACT: 0 none, 1 relu, 2 lrelu; RND: tf32-round outputs (for next conv layer).
template<int CINL, int ACT, int RND>
__global__ void __launch_bounds__(128,2)
conv5_mma(const float* __restrict__ in, const float* __restrict__ wrec,
          const float* __restrict__ bias, float* __restrict__ out,
          int coutR, int MBt){
    extern __shared__ __align__(16) char smem[];
    float* wsm  = reinterpret_cast<float*>(smem);           // 2 x 1024 floats
    float* actm = reinterpret_cast<float*>(smem + 8192);    // 16*840 floats
    const uint32_t wsmA  = smem_u32(wsm);
    const uint32_t actmA = smem_u32(actm);

    const int tid = threadIdx.x, lane = tid&31, wy = tid>>5;
    const int y0 = blockIdx.x*4, b = blockIdx.y, oc0 = blockIdx.z*64;
    const int mb0 = oc0 >> 4;           // first m16-record index
    constexpr int KG = CINL/8;

    float acc[4][12][4];
#pragma unroll
    for(int m=0;m<4;m++)
#pragma unroll
        for(int n=0;n<12;n++)
#pragma unroll
            for(int k=0;k<4;k++) acc[m][n][k]=0.f;

    const float* inB = in + (size_t)b*CINL*(HWD*HWD);

    for(int ch=0; ch<CINL/16; ch++){
        __syncthreads();   // prev chunk compute done (act WAR)
        // ---- fill act: thread = (kc, irow) pair; plane stride 840 words ----
        {
            int kc = tid>>3, irow = tid&7;
            int gy = y0 + irow - 2;
            uint32_t dst = actmA + (uint32_t)(kc*840 + irow*104)*4;
            if((unsigned)gy < 96u){
                // zero halo edges x_pad {0,1} and {98..103}
                asm volatile("st.shared.v2.b32 [%0],{%1,%1};"::"r"(dst),"r"(0):"memory");
                asm volatile("st.shared.v2.b32 [%0],{%1,%1};"::"r"(dst+392),"r"(0):"memory");
                asm volatile("st.shared.v2.b32 [%0],{%1,%1};"::"r"(dst+400),"r"(0):"memory");
                asm volatile("st.shared.v2.b32 [%0],{%1,%1};"::"r"(dst+408),"r"(0):"memory");
                const float* src = inB + ((size_t)(ch*16+kc)*HWD + gy)*HWD;
#pragma unroll
                for(int j=0;j<48;j++) CPA8(dst + 8 + j*8, src + j*2);
            } else {
#pragma unroll
                for(int j=0;j<26;j++)
                    asm volatile("st.shared.v4.b32 [%0],{%1,%1,%1,%1};"::"r"(dst+j*16),"r"(0):"memory");
            }
        }
        // ---- stage weights tap 0 into buf 0 ----
        {
            int rec16 = tid>>4, part = tid&15;      // 8 recs x 16 parts(32B)
            int kg2 = rec16>>2, mb = rec16&3;
            const float* gs = wrec + (((size_t)(0*KG + ch*2 + kg2))*MBt + mb0 + mb)*128 + part*8;
            uint32_t sd = wsmA + (uint32_t)((rec16*128 + part*8))*4;
            CPA16(sd, gs); CPA16(sd+16, gs+4);
        }
        CP_COMMIT(); CP_WAITG0();
        __syncthreads();

        for(int tap=0; tap<25; tap++){
            const int buf = tap&1, ky = tap/5, kx = tap%5;
            __syncthreads();   // compute(tap-1) done everywhere (wsm WAR)
            if(tap<24){
                int rec16 = tid>>4, part = tid&15;
                int kg2 = rec16>>2, mb = rec16&3;
                const float* gs = wrec + (((size_t)((tap+1)*KG + ch*2 + kg2))*MBt + mb0 + mb)*128 + part*8;
                uint32_t sd = wsmA + (uint32_t)(((1-buf)*1024 + rec16*128 + part*8))*4;
                CPA16(sd, gs); CPA16(sd+16, gs+4);
                CP_COMMIT(); CP_WAITG1();
            } else { CP_WAITG0(); }
            __syncthreads();   // staged buf visible

#pragma unroll
            for(int kg2=0; kg2<2; kg2++){
                uint32_t A[4][4];
#pragma unroll
                for(int m=0;m<4;m++){
                    const uint4 av = reinterpret_cast<const uint4*>(wsm + buf*1024 + (kg2*4+m)*128)[lane];
                    A[m][0]=av.x; A[m][1]=av.y; A[m][2]=av.z; A[m][3]=av.w;
                }
                const float* ap = actm + (kg2*8 + (lane&3))*840 + (wy+ky)*104 + (lane>>2) + kx;
#pragma unroll
                for(int nb=0; nb<12; nb++){
                    uint32_t b0 = __float_as_uint(ap[nb*8]);
                    uint32_t b1 = __float_as_uint(ap[nb*8 + 3360]);   // +4 planes
#pragma unroll
                    for(int m=0;m<4;m++) mma8(acc[m][nb], A[m], b0, b1);
                }
            }
        }
    }

    // ---- epilogue: c0(g,2t) c1(g,2t+1) c2(g+8,2t) c3(g+8,2t+1) ----
#pragma unroll
    for(int m=0;m<4;m++){
        int ocm = oc0 + m*16 + (lane>>2);
#pragma unroll
        for(int h=0;h<2;h++){
            int oc = ocm + h*8;
            if(oc < coutR){
                float bv = bias[oc];
                float* row = out + ((size_t)(b*coutR + oc)*HWD + (y0+wy))*HWD;
#pragma unroll
                for(int nb=0; nb<12; nb++){
                    float c0 = acc[m][nb][h*2+0] + bv;
                    float c1 = acc[m][nb][h*2+1] + bv;
                    if(ACT==1){ c0=fmaxf(c0,0.f); c1=fmaxf(c1,0.f); }
                    if(ACT==2){ c0=(c0>=0.f)?c0:0.01f*c0; c1=(c1>=0.f)?c1:0.01f*c1; }
                    if(RND){ c0=to_tf32(c0); c1=to_tf32(c1); }
                    *reinterpret_cast<float2*>(row + nb*8 + (lane&3)*2) = make_float2(c0,c1);
                }
            }
        }
    }
}

// ---------- global max ----------
__global__ void maxred_kernel(const float* __restrict__ x, float* __restrict__ gmax){
    __shared__ float sm[256];
    int bc=blockIdx.x;
    const float* p = x + (size_t)bc*HWD*HWD;
    float m=-3.402823466e38f;
    for(int i=threadIdx.x;i<HWD*HWD;i+=256) m=fmaxf(m,p[i]);
    sm[threadIdx.x]=m; __syncthreads();
    for(int st=128;st>0;st>>=1){ if(threadIdx.x<st) sm[threadIdx.x]=fmaxf(sm[threadIdx.x],sm[threadIdx.x+st]); __syncthreads(); }
    if(threadIdx.x==0) gmax[bc]=sm[0];
}

// ---------- lrelu -> 1x1 conv 576 -> grouped softmax ----------
__global__ void weights_kernel(const float* __restrict__ gmax, const float* __restrict__ ww3,
                               const float* __restrict__ bw3, float* __restrict__ outw){
    __shared__ float gsm[576]; __shared__ float osm[576];
    int b=blockIdx.x, t=threadIdx.x;
    float x=gmax[b*576+t];
    gsm[t]=(x>=0.f)?x:0.01f*x;
    __syncthreads();
    float a=bw3[t];
    const float* wr=ww3+(size_t)t*576;
    for(int i=0;i<576;i++) a=fmaf(wr[i],gsm[i],a);
    osm[t]=a; __syncthreads();
    if(t<192){
        float p=osm[t],q=osm[192+t],r=osm[384+t];
        float mx=fmaxf(p,fmaxf(q,r));
        float ep=expf(p-mx),eq=expf(q-mx),er=expf(r-mx);
        float inv=1.f/(ep+eq+er);
        outw[b*576+t]=ep*inv; outw[b*576+192+t]=eq*inv; outw[b*576+384+t]=er*inv;
    }
}

// ---------- launch ----------
static const int CONV_SMEM = 8192 + 16*840*4;   // 61952

extern "C" void kernel_launch(void* const* d_in, const int* in_sizes, int n_in, void* d_out, int out_size){
    const float* z2=(const float*)d_in[0];  const float* y1=(const float*)d_in[1];
    const float* ws1=(const float*)d_in[2]; const float* bs1=(const float*)d_in[3];
    const float* ws2=(const float*)d_in[4]; const float* bs2=(const float*)d_in[5];
    const float* ws3=(const float*)d_in[6]; const float* bs3=(const float*)d_in[7];
    const float* wm1=(const float*)d_in[8]; const float* bm1=(const float*)d_in[9];
    const float* wm2=(const float*)d_in[10];const float* bm2=(const float*)d_in[11];
    const float* wm3=(const float*)d_in[12];const float* bm3=(const float*)d_in[13];
    const float* ww1=(const float*)d_in[14];const float* bw1=(const float*)d_in[15];
    const float* ww2=(const float*)d_in[16];const float* bw2=(const float*)d_in[17];
    const float* ww3=(const float*)d_in[18];const float* bw3=(const float*)d_in[19];
    float* out=(float*)d_out;

    float *cat,*h1,*h2,*ww2o,*gmax,*wtb;
    cudaGetSymbolAddress((void**)&cat,g_cat);
    cudaGetSymbolAddress((void**)&h1,g_h1);
    cudaGetSymbolAddress((void**)&h2,g_h2);
    cudaGetSymbolAddress((void**)&ww2o,g_ww2);
    cudaGetSymbolAddress((void**)&gmax,g_gmax);
    cudaGetSymbolAddress((void**)&wtb,g_wt);

    cudaFuncSetAttribute(conv5_mma<320,1,1>, cudaFuncAttributeMaxDynamicSharedMemorySize, CONV_SMEM);
    cudaFuncSetAttribute(conv5_mma<320,2,1>, cudaFuncAttributeMaxDynamicSharedMemorySize, CONV_SMEM);
    cudaFuncSetAttribute(conv5_mma<128,1,1>, cudaFuncAttributeMaxDynamicSharedMemorySize, CONV_SMEM);
    cudaFuncSetAttribute(conv5_mma<128,2,1>, cudaFuncAttributeMaxDynamicSharedMemorySize, CONV_SMEM);
    cudaFuncSetAttribute(conv5_mma<128,1,0>, cudaFuncAttributeMaxDynamicSharedMemorySize, CONV_SMEM);
    cudaFuncSetAttribute(conv5_mma<128,0,0>, cudaFuncAttributeMaxDynamicSharedMemorySize, CONV_SMEM);

    const size_t MEA_OFF=(size_t)NB*576*HWD*HWD;
    const size_t WGT_OFF=2*MEA_OFF;

    // frag-ordered weight prep. sizes (floats): (320,128):1,024,000 (128,128):409,600 (128,576):1,843,200
    const size_t O_S1=0, O_M1=1024000, O_W1=2048000, O_S2=3072000, O_M2=3481600,
                 O_S3=3891200, O_M3=5734400, O_W2=7577600;
    auto wprep=[&](const float* w, size_t off, int cin, int cout){
        int KG=cin/8, MBt=cout/16;
        long tot=(long)25*KG*MBt*32;
        wtrans_kernel<<<(int)((tot+255)/256),256>>>(w, wtb+off, cin, KG, MBt);
    };
    wprep(ws1,O_S1,320,128); wprep(wm1,O_M1,320,128); wprep(ww1,O_W1,320,128);
    wprep(ws2,O_S2,128,128); wprep(wm2,O_M2,128,128);
    wprep(ws3,O_S3,128,576); wprep(wm3,O_M3,128,576); wprep(ww2,O_W2,128,576);

    { long tot=(long)NB*320*HWD*HWD; upcat_kernel<<<(int)((tot+255)/256),256>>>(z2,y1,cat); }

    dim3 blk(128);
    dim3 g128(24,NB,2), g576(24,NB,9);

    conv5_mma<320,1,1><<<g128,blk,CONV_SMEM>>>(cat, wtb+O_S1, bs1, h1, 128, 8);
    conv5_mma<128,1,1><<<g128,blk,CONV_SMEM>>>(h1,  wtb+O_S2, bs2, h2, 128, 8);
    conv5_mma<128,1,0><<<g576,blk,CONV_SMEM>>>(h2,  wtb+O_S3, bs3, out, 576, 36);

    conv5_mma<320,2,1><<<g128,blk,CONV_SMEM>>>(cat, wtb+O_M1, bm1, h1, 128, 8);
    conv5_mma<128,2,1><<<g128,blk,CONV_SMEM>>>(h1,  wtb+O_M2, bm2, h2, 128, 8);
    conv5_mma<128,0,0><<<g576,blk,CONV_SMEM>>>(h2,  wtb+O_M3, bm3, out+MEA_OFF, 576, 36);

    conv5_mma<320,2,1><<<g128,blk,CONV_SMEM>>>(cat, wtb+O_W1, bw1, h1, 128, 8);
    conv5_mma<128,0,0><<<g576,blk,CONV_SMEM>>>(h1,  wtb+O_W2, bw2, ww2o, 576, 36);
    maxred_kernel<<<NB*576,256>>>(ww2o,gmax);
    weights_kernel<<<NB,576>>>(gmax,ww3,bw3,out+WGT_OFF);
}

// round 8
// speedup vs baseline: 4.4951x; 1.1971x over previous
#include <cuda_runtime.h>
#include <cstdint>
#include <math.h>

#define HWD 96
#define NB 8

__device__ float g_cat[(size_t)NB*320*HWD*HWD];
__device__ float g_h1[(size_t)NB*128*HWD*HWD];
__device__ float g_h2[(size_t)NB*128*HWD*HWD];
__device__ float g_ww2[(size_t)NB*576*HWD*HWD];
__device__ float g_gmax[NB*576];
__device__ float g_wt[10035200];   // frag-ordered, tf32-rounded weights

// ---------- helpers ----------
__device__ __forceinline__ float to_tf32(float x){ float r; asm("cvt.rna.tf32.f32 %0,%1;":"=f"(r):"f"(x)); return r; }

#define CPA8(d,s)   asm volatile("cp.async.ca.shared.global [%0],[%1],8;"::"r"(d),"l"(s):"memory")
#define CPA16(d,s)  asm volatile("cp.async.ca.shared.global [%0],[%1],16;"::"r"(d),"l"(s):"memory")
#define CP_COMMIT() asm volatile("cp.async.commit_group;":::"memory")
#define CP_WAITG0() asm volatile("cp.async.wait_group 0;":::"memory")

__device__ __forceinline__ uint32_t smem_u32(const void* p){
    uint32_t a; asm("{ .reg .u64 t; cvta.to.shared.u64 t, %1; cvt.u32.u64 %0, t; }":"=r"(a):"l"(p)); return a;
}

// tf32 m16n8k8 mma.sync (sm_80+ portable PTX -> tensor pipe)
__device__ __forceinline__ void mma8(float* c, const uint32_t* a, uint32_t b0, uint32_t b1){
    asm volatile("mma.sync.aligned.m16n8k8.row.col.f32.tf32.tf32.f32 "
        "{%0,%1,%2,%3},{%4,%5,%6,%7},{%8,%9},{%0,%1,%2,%3};"
        : "+f"(c[0]),"+f"(c[1]),"+f"(c[2]),"+f"(c[3])
        : "r"(a[0]),"r"(a[1]),"r"(a[2]),"r"(a[3]),"r"(b0),"r"(b1));
}

// ---------- upsample+concat (tf32 rounded) ----------
__global__ void upcat_kernel(const float* __restrict__ z2, const float* __restrict__ y1, float* __restrict__ cat){
    long idx = (long)blockIdx.x*blockDim.x + threadIdx.x;
    const long total = (long)NB*320*HWD*HWD;
    if(idx>=total) return;
    int X=(int)(idx%HWD); long t=idx/HWD; int Y=(int)(t%HWD); t/=HWD; int c=(int)(t%320); int b=(int)(t/320);
    float v;
    if(c<128){
        const float S=23.0f/95.0f; float fy=Y*S, fx=X*S;
        int y0=(int)fy, x0=(int)fx; int y1i=min(y0+1,23), x1i=min(x0+1,23);
        float wy=fy-(float)y0, wx=fx-(float)x0;
        const float* p = z2 + ((size_t)(b*128+c)*24)*24;
        float a=p[y0*24+x0], bq=p[y0*24+x1i], cq=p[y1i*24+x0], dq=p[y1i*24+x1i];
        float top=a*(1.f-wx)+bq*wx, bot=cq*(1.f-wx)+dq*wx;
        v = top*(1.f-wy)+bot*wy;
    } else v = y1[((size_t)(b*192+(c-128))*HWD+Y)*HWD+X];
    cat[idx] = to_tf32(v);
}

// ---------- merged weight prep (all 8 layers, one launch) ----------
// record = ((tap*KG + kg)*MBt + mb): 32 lanes x float4:
//   oc = mb*16 + (l>>2), cin = kg*8 + (l&3)
//   {W(oc,cin), W(oc+8,cin), W(oc,cin+4), W(oc+8,cin+4)}  (tf32-rounded)
struct WT8 {
    const float* w[8];
    long off[8];      // float offset into g_wt
    long recEnd[8];   // cumulative record counts
    int cin[8], KG[8], MBt[8];
};
__global__ void wtrans_all(WT8 T, float* __restrict__ wt, long totalThr){
    long idx = (long)blockIdx.x*blockDim.x + threadIdx.x;
    if(idx >= totalThr) return;
    int l = (int)(idx&31); long rec = idx>>5;
    int L = 0;
    while(rec >= T.recEnd[L]) L++;
    long rl = rec - (L ? T.recEnd[L-1] : 0);
    const int MBt = T.MBt[L], KG = T.KG[L], cin = T.cin[L];
    int mb = (int)(rl % MBt); long r2 = rl / MBt;
    int kg = (int)(r2 % KG); int tap = (int)(r2 / KG);
    const float* w = T.w[L];
    int oc = mb*16 + (l>>2), c = kg*8 + (l&3);
    float4 v;
    v.x = to_tf32(w[((size_t)oc*cin + c)*25 + tap]);
    v.y = to_tf32(w[((size_t)(oc+8)*cin + c)*25 + tap]);
    v.z = to_tf32(w[((size_t)oc*cin + c+4)*25 + tap]);
    v.w = to_tf32(w[((size_t)(oc+8)*cin + c+4)*25 + tap]);
    reinterpret_cast<float4*>(wt + T.off[L] + rl*128)[l] = v;
}

// ---------- tf32 mma.sync implicit-GEMM 5x5 conv (pad=2), ky-row weight grouping ----------
// Block: 128 thr = 4 warps; warp wy covers output row y0+wy, all 96 x, 64 oc.
// smem: [0..40960) weight dbuf (2 x 20KB = 5 taps x 40 records), [40960..) act 16 planes x 840 words.
// One __syncthreads per 5-tap group (was 2 per tap).
template<int CINL, int ACT, int RND>
__global__ void __launch_bounds__(128,2)
conv5_mma(const float* __restrict__ in, const float* __restrict__ wrec,
          const float* __restrict__ bias, float* __restrict__ out,
          int coutR, int MBt){
    extern __shared__ __align__(16) char smem[];
    float* wsm  = reinterpret_cast<float*>(smem);            // 2 x 5120 floats
    float* actm = reinterpret_cast<float*>(smem + 40960);    // 16*840 floats
    const uint32_t wsmA  = smem_u32(wsm);
    const uint32_t actmA = smem_u32(actm);

    const int tid = threadIdx.x, lane = tid&31, wy = tid>>5;
    const int y0 = blockIdx.x*4, b = blockIdx.y, oc0 = blockIdx.z*64;
    const int mb0 = oc0 >> 4;
    constexpr int KG = CINL/8;

    float acc[4][12][4];
#pragma unroll
    for(int m=0;m<4;m++)
#pragma unroll
        for(int n=0;n<12;n++)
#pragma unroll
            for(int k=0;k<4;k++) acc[m][n][k]=0.f;

    const float* inB = in + (size_t)b*CINL*(HWD*HWD);

    for(int ch=0; ch<CINL/16; ch++){
        // ---- fill act: thread = (kc, irow); plane stride 840 words ----
        {
            int kc = tid>>3, irow = tid&7;
            int gy = y0 + irow - 2;
            uint32_t dst = actmA + (uint32_t)(kc*840 + irow*104)*4;
            if((unsigned)gy < 96u){
                asm volatile("st.shared.v2.b32 [%0],{%1,%1};"::"r"(dst),"r"(0):"memory");
                asm volatile("st.shared.v2.b32 [%0],{%1,%1};"::"r"(dst+392),"r"(0):"memory");
                asm volatile("st.shared.v2.b32 [%0],{%1,%1};"::"r"(dst+400),"r"(0):"memory");
                asm volatile("st.shared.v2.b32 [%0],{%1,%1};"::"r"(dst+408),"r"(0):"memory");
                const float* src = inB + ((size_t)(ch*16+kc)*HWD + gy)*HWD;
#pragma unroll
                for(int j=0;j<48;j++) CPA8(dst + 8 + j*8, src + j*2);
            } else {
#pragma unroll
                for(int j=0;j<26;j++)
                    asm volatile("st.shared.v4.b32 [%0],{%1,%1,%1,%1};"::"r"(dst+j*16),"r"(0):"memory");
            }
        }
        // ---- stage group 0 weights (taps 0..4) into buf 0: 1280 float4 tasks ----
        {
#pragma unroll
            for(int i=0;i<10;i++){
                int f4 = tid + i*128;
                int rec = f4>>5, l = f4&31;
                int tloc = rec>>3, r8 = rec&7;
                int kg2 = r8>>2, mb = r8&3;
                const float* gs = wrec + (((size_t)(tloc)*KG + ch*2 + kg2)*MBt + mb0 + mb)*128 + l*4;
                CPA16(wsmA + (uint32_t)(rec*512 + l*16), gs);
            }
        }
        CP_COMMIT(); CP_WAITG0();
        __syncthreads();   // act + buf0 visible; also prev-chunk WAR (prior grp=4 sync chain)

        for(int grp=0; grp<5; grp++){
            const int buf = grp&1;
            if(grp<4){
#pragma unroll
                for(int i=0;i<10;i++){
                    int f4 = tid + i*128;
                    int rec = f4>>5, l = f4&31;
                    int tloc = rec>>3, r8 = rec&7;
                    int kg2 = r8>>2, mb = r8&3;
                    const float* gs = wrec + (((size_t)((grp+1)*5 + tloc)*KG + ch*2 + kg2)*MBt + mb0 + mb)*128 + l*4;
                    CPA16(wsmA + (uint32_t)((1-buf)*20480 + rec*512 + l*16), gs);
                }
                CP_COMMIT();
            }
            // ---- compute 5 taps from buf (ky = grp, kx = tloc) ----
#pragma unroll
            for(int tloc=0; tloc<5; tloc++){
#pragma unroll
                for(int kg2=0; kg2<2; kg2++){
                    uint32_t A[4][4];
#pragma unroll
                    for(int m=0;m<4;m++){
                        const uint4 av = reinterpret_cast<const uint4*>(
                            wsm + buf*5120 + tloc*1024 + (kg2*4+m)*128)[lane];
                        A[m][0]=av.x; A[m][1]=av.y; A[m][2]=av.z; A[m][3]=av.w;
                    }
                    const float* ap = actm + (kg2*8 + (lane&3))*840 + (wy+grp)*104 + (lane>>2) + tloc;
#pragma unroll
                    for(int nb=0; nb<12; nb++){
                        uint32_t b0 = __float_as_uint(ap[nb*8]);
                        uint32_t b1 = __float_as_uint(ap[nb*8 + 3360]);   // +4 planes
#pragma unroll
                        for(int m=0;m<4;m++) mma8(acc[m][nb], A[m], b0, b1);
                    }
                }
            }
            if(grp<4) CP_WAITG0();
            __syncthreads();   // all warps done with buf; staged (1-buf) visible
        }
    }

    // ---- epilogue ----
#pragma unroll
    for(int m=0;m<4;m++){
        int ocm = oc0 + m*16 + (lane>>2);
#pragma unroll
        for(int h=0;h<2;h++){
            int oc = ocm + h*8;
            if(oc < coutR){
                float bv = bias[oc];
                float* row = out + ((size_t)(b*coutR + oc)*HWD + (y0+wy))*HWD;
#pragma unroll
                for(int nb=0; nb<12; nb++){
                    float c0 = acc[m][nb][h*2+0] + bv;
                    float c1 = acc[m][nb][h*2+1] + bv;
                    if(ACT==1){ c0=fmaxf(c0,0.f); c1=fmaxf(c1,0.f); }
                    if(ACT==2){ c0=(c0>=0.f)?c0:0.01f*c0; c1=(c1>=0.f)?c1:0.01f*c1; }
                    if(RND){ c0=to_tf32(c0); c1=to_tf32(c1); }
                    *reinterpret_cast<float2*>(row + nb*8 + (lane&3)*2) = make_float2(c0,c1);
                }
            }
        }
    }
}

// ---------- global max ----------
__global__ void maxred_kernel(const float* __restrict__ x, float* __restrict__ gmax){
    __shared__ float sm[256];
    int bc=blockIdx.x;
    const float* p = x + (size_t)bc*HWD*HWD;
    float m=-3.402823466e38f;
    for(int i=threadIdx.x;i<HWD*HWD;i+=256) m=fmaxf(m,p[i]);
    sm[threadIdx.x]=m; __syncthreads();
    for(int st=128;st>0;st>>=1){ if(threadIdx.x<st) sm[threadIdx.x]=fmaxf(sm[threadIdx.x],sm[threadIdx.x+st]); __syncthreads(); }
    if(threadIdx.x==0) gmax[bc]=sm[0];
}

// ---------- lrelu -> 1x1 conv 576 -> grouped softmax ----------
__global__ void weights_kernel(const float* __restrict__ gmax, const float* __restrict__ ww3,
                               const float* __restrict__ bw3, float* __restrict__ outw){
    __shared__ float gsm[576]; __shared__ float osm[576];
    int b=blockIdx.x, t=threadIdx.x;
    float x=gmax[b*576+t];
    gsm[t]=(x>=0.f)?x:0.01f*x;
    __syncthreads();
    float a=bw3[t];
    const float* wr=ww3+(size_t)t*576;
    for(int i=0;i<576;i++) a=fmaf(wr[i],gsm[i],a);
    osm[t]=a; __syncthreads();
    if(t<192){
        float p=osm[t],q=osm[192+t],r=osm[384+t];
        float mx=fmaxf(p,fmaxf(q,r));
        float ep=expf(p-mx),eq=expf(q-mx),er=expf(r-mx);
        float inv=1.f/(ep+eq+er);
        outw[b*576+t]=ep*inv; outw[b*576+192+t]=eq*inv; outw[b*576+384+t]=er*inv;
    }
}

// ---------- launch ----------
static const int CONV_SMEM = 40960 + 16*840*4;   // 94720

extern "C" void kernel_launch(void* const* d_in, const int* in_sizes, int n_in, void* d_out, int out_size){
    const float* z2=(const float*)d_in[0];  const float* y1=(const float*)d_in[1];
    const float* ws1=(const float*)d_in[2]; const float* bs1=(const float*)d_in[3];
    const float* ws2=(const float*)d_in[4]; const float* bs2=(const float*)d_in[5];
    const float* ws3=(const float*)d_in[6]; const float* bs3=(const float*)d_in[7];
    const float* wm1=(const float*)d_in[8]; const float* bm1=(const float*)d_in[9];
    const float* wm2=(const float*)d_in[10];const float* bm2=(const float*)d_in[11];
    const float* wm3=(const float*)d_in[12];const float* bm3=(const float*)d_in[13];
    const float* ww1=(const float*)d_in[14];const float* bw1=(const float*)d_in[15];
    const float* ww2=(const float*)d_in[16];const float* bw2=(const float*)d_in[17];
    const float* ww3=(const float*)d_in[18];const float* bw3=(const float*)d_in[19];
    float* out=(float*)d_out;

    float *cat,*h1,*h2,*ww2o,*gmax,*wtb;
    cudaGetSymbolAddress((void**)&cat,g_cat);
    cudaGetSymbolAddress((void**)&h1,g_h1);
    cudaGetSymbolAddress((void**)&h2,g_h2);
    cudaGetSymbolAddress((void**)&ww2o,g_ww2);
    cudaGetSymbolAddress((void**)&gmax,g_gmax);
    cudaGetSymbolAddress((void**)&wtb,g_wt);

    cudaFuncSetAttribute(conv5_mma<320,1,1>, cudaFuncAttributeMaxDynamicSharedMemorySize, CONV_SMEM);
    cudaFuncSetAttribute(conv5_mma<320,2,1>, cudaFuncAttributeMaxDynamicSharedMemorySize, CONV_SMEM);
    cudaFuncSetAttribute(conv5_mma<128,1,1>, cudaFuncAttributeMaxDynamicSharedMemorySize, CONV_SMEM);
    cudaFuncSetAttribute(conv5_mma<128,2,1>, cudaFuncAttributeMaxDynamicSharedMemorySize, CONV_SMEM);
    cudaFuncSetAttribute(conv5_mma<128,1,0>, cudaFuncAttributeMaxDynamicSharedMemorySize, CONV_SMEM);
    cudaFuncSetAttribute(conv5_mma<128,0,0>, cudaFuncAttributeMaxDynamicSharedMemorySize, CONV_SMEM);

    const size_t MEA_OFF=(size_t)NB*576*HWD*HWD;
    const size_t WGT_OFF=2*MEA_OFF;

    // merged weight prep (1 launch). rec counts: 8000x3, 3200x2, 14400x3 = 73600 recs.
    const long O_S1=0, O_M1=1024000, O_W1=2048000, O_S2=3072000, O_M2=3481600,
               O_S3=3891200, O_M3=5734400, O_W2=7577600;
    {
        WT8 T;
        const float* ws[8] = {ws1,wm1,ww1,ws2,wm2,ws3,wm3,ww2};
        long offs[8]   = {O_S1,O_M1,O_W1,O_S2,O_M2,O_S3,O_M3,O_W2};
        int cins[8]    = {320,320,320,128,128,128,128,128};
        int couts[8]   = {128,128,128,128,128,576,576,576};
        long cum = 0;
        for(int i=0;i<8;i++){
            T.w[i]=ws[i]; T.off[i]=offs[i]; T.cin[i]=cins[i];
            T.KG[i]=cins[i]/8; T.MBt[i]=couts[i]/16;
            cum += 25L*T.KG[i]*T.MBt[i];
            T.recEnd[i]=cum;
        }
        long totalThr = cum*32;
        wtrans_all<<<(int)((totalThr+255)/256),256>>>(T, wtb, totalThr);
    }

    { long tot=(long)NB*320*HWD*HWD; upcat_kernel<<<(int)((tot+255)/256),256>>>(z2,y1,cat); }

    dim3 blk(128);
    dim3 g128(24,NB,2), g576(24,NB,9);

    // sigma branch
    conv5_mma<320,1,1><<<g128,blk,CONV_SMEM>>>(cat, wtb+O_S1, bs1, h1, 128, 8);
    conv5_mma<128,1,1><<<g128,blk,CONV_SMEM>>>(h1,  wtb+O_S2, bs2, h2, 128, 8);
    conv5_mma<128,1,0><<<g576,blk,CONV_SMEM>>>(h2,  wtb+O_S3, bs3, out, 576, 36);

    // means branch (m1 is the 6th launch -> ncu -s 5 -c 1 captures a real conv)
    conv5_mma<320,2,1><<<g128,blk,CONV_SMEM>>>(cat, wtb+O_M1, bm1, h1, 128, 8);
    conv5_mma<128,2,1><<<g128,blk,CONV_SMEM>>>(h1,  wtb+O_M2, bm2, h2, 128, 8);
    conv5_mma<128,0,0><<<g576,blk,CONV_SMEM>>>(h2,  wtb+O_M3, bm3, out+MEA_OFF, 576, 36);

    // weights branch
    conv5_mma<320,2,1><<<g128,blk,CONV_SMEM>>>(cat, wtb+O_W1, bw1, h1, 128, 8);
    conv5_mma<128,0,0><<<g576,blk,CONV_SMEM>>>(h1,  wtb+O_W2, bw2, ww2o, 576, 36);
    maxred_kernel<<<NB*576,256>>>(ww2o,gmax);
    weights_kernel<<<NB,576>>>(gmax,ww3,bw3,out+WGT_OFF);
}

// round 11
// speedup vs baseline: 4.8539x; 1.0798x over previous
#include <cuda_runtime.h>
#include <cstdint>
#include <math.h>

#define HWD 96
#define NB 8

__device__ float g_cat[(size_t)NB*320*HWD*HWD];
__device__ float g_h1s[(size_t)NB*128*HWD*HWD];
__device__ float g_h1m[(size_t)NB*128*HWD*HWD];
__device__ float g_h1w[(size_t)NB*128*HWD*HWD];
__device__ float g_h2s[(size_t)NB*128*HWD*HWD];
__device__ float g_h2m[(size_t)NB*128*HWD*HWD];
__device__ float g_ww2[(size_t)NB*576*HWD*HWD];
__device__ float g_gmax[NB*576];
__device__ float g_wt[10035200];   // frag-ordered, tf32-rounded weights

// ---------- helpers ----------
__device__ __forceinline__ float to_tf32(float x){ float r; asm("cvt.rna.tf32.f32 %0,%1;":"=f"(r):"f"(x)); return r; }

#define CPA8(d,s)   asm volatile("cp.async.ca.shared.global [%0],[%1],8;"::"r"(d),"l"(s):"memory")
#define CPA16(d,s)  asm volatile("cp.async.ca.shared.global [%0],[%1],16;"::"r"(d),"l"(s):"memory")
#define CP_COMMIT() asm volatile("cp.async.commit_group;":::"memory")
#define CP_WAITG0() asm volatile("cp.async.wait_group 0;":::"memory")

__device__ __forceinline__ uint32_t smem_u32(const void* p){
    uint32_t a; asm("{ .reg .u64 t; cvta.to.shared.u64 t, %1; cvt.u32.u64 %0, t; }":"=r"(a):"l"(p)); return a;
}

// tf32 m16n8k8 mma.sync (sm_80+ portable PTX -> tensor pipe)
__device__ __forceinline__ void mma8(float* c, const uint32_t* a, uint32_t b0, uint32_t b1){
    asm volatile("mma.sync.aligned.m16n8k8.row.col.f32.tf32.tf32.f32 "
        "{%0,%1,%2,%3},{%4,%5,%6,%7},{%8,%9},{%0,%1,%2,%3};"
        : "+f"(c[0]),"+f"(c[1]),"+f"(c[2]),"+f"(c[3])
        : "r"(a[0]),"r"(a[1]),"r"(a[2]),"r"(a[3]),"r"(b0),"r"(b1));
}

// ---------- upsample+concat (tf32 rounded) ----------
__global__ void upcat_kernel(const float* __restrict__ z2, const float* __restrict__ y1, float* __restrict__ cat){
    long idx = (long)blockIdx.x*blockDim.x + threadIdx.x;
    const long total = (long)NB*320*HWD*HWD;
    if(idx>=total) return;
    int X=(int)(idx%HWD); long t=idx/HWD; int Y=(int)(t%HWD); t/=HWD; int c=(int)(t%320); int b=(int)(t/320);
    float v;
    if(c<128){
        const float S=23.0f/95.0f; float fy=Y*S, fx=X*S;
        int y0=(int)fy, x0=(int)fx; int y1i=min(y0+1,23), x1i=min(x0+1,23);
        float wy=fy-(float)y0, wx=fx-(float)x0;
        const float* p = z2 + ((size_t)(b*128+c)*24)*24;
        float a=p[y0*24+x0], bq=p[y0*24+x1i], cq=p[y1i*24+x0], dq=p[y1i*24+x1i];
        float top=a*(1.f-wx)+bq*wx, bot=cq*(1.f-wx)+dq*wx;
        v = top*(1.f-wy)+bot*wy;
    } else v = y1[((size_t)(b*192+(c-128))*HWD+Y)*HWD+X];
    cat[idx] = to_tf32(v);
}

// ---------- merged weight prep (all 8 layers, one launch) ----------
struct WT8 {
    const float* w[8];
    long off[8];
    long recEnd[8];
    int cin[8], KG[8], MBt[8];
};
__global__ void wtrans_all(WT8 T, float* __restrict__ wt, long totalThr){
    long idx = (long)blockIdx.x*blockDim.x + threadIdx.x;
    if(idx >= totalThr) return;
    int l = (int)(idx&31); long rec = idx>>5;
    int L = 0;
    while(rec >= T.recEnd[L]) L++;
    long rl = rec - (L ? T.recEnd[L-1] : 0);
    const int MBt = T.MBt[L], KG = T.KG[L], cin = T.cin[L];
    int mb = (int)(rl % MBt); long r2 = rl / MBt;
    int kg = (int)(r2 % KG); int tap = (int)(r2 / KG);
    const float* w = T.w[L];
    int oc = mb*16 + (l>>2), c = kg*8 + (l&3);
    float4 v;
    v.x = to_tf32(w[((size_t)oc*cin + c)*25 + tap]);
    v.y = to_tf32(w[((size_t)(oc+8)*cin + c)*25 + tap]);
    v.z = to_tf32(w[((size_t)oc*cin + c+4)*25 + tap]);
    v.w = to_tf32(w[((size_t)(oc+8)*cin + c+4)*25 + tap]);
    reinterpret_cast<float4*>(wt + T.off[L] + rl*128)[l] = v;
}

// ---------- table-driven conv stage ----------
struct ConvSlice {
    const float* in;     // input feature map base
    float*       outp;   // output feature map base
    const float* wrec;   // frag-ordered weights for this layer
    const float* bias;
    int mb0;             // first m16 record (= octile*4)
    int MBt;             // records per (tap,kg) row = cout/16
    int cout;            // logical output channels (stride of out tensor)
    int actrnd;          // act | (rnd<<4); act: 0 none, 1 relu, 2 lrelu
};
struct ConvTable { ConvSlice s[18]; };

// Block: 128 thr = 4 warps; warp wy covers output row y0+wy, all 96 x, 64 oc.
// smem: [0..40960) weight dbuf (2 x 20KB), [40960..) act 16 planes x 840 words.
template<int CINL>
__global__ void __launch_bounds__(128,2)
conv5_stage(ConvTable T){
    extern __shared__ __align__(16) char smem[];
    float* wsm  = reinterpret_cast<float*>(smem);            // 2 x 5120 floats
    float* actm = reinterpret_cast<float*>(smem + 40960);    // 16*840 floats
    const uint32_t wsmA  = smem_u32(wsm);
    const uint32_t actmA = smem_u32(actm);

    const ConvSlice S = T.s[blockIdx.z];
    const int tid = threadIdx.x, lane = tid&31, wy = tid>>5;
    const int y0 = blockIdx.x*4, b = blockIdx.y;
    const int mb0 = S.mb0, MBt = S.MBt;
    constexpr int KG = CINL/8;

    float acc[4][12][4];
#pragma unroll
    for(int m=0;m<4;m++)
#pragma unroll
        for(int n=0;n<12;n++)
#pragma unroll
            for(int k=0;k<4;k++) acc[m][n][k]=0.f;

    const float* inB = S.in + (size_t)b*CINL*(HWD*HWD);
    const float* wrec = S.wrec;

    for(int ch=0; ch<CINL/16; ch++){
        // ---- fill act: thread = (kc, irow); plane stride 840 words ----
        {
            int kc = tid>>3, irow = tid&7;
            int gy = y0 + irow - 2;
            uint32_t dst = actmA + (uint32_t)(kc*840 + irow*104)*4;
            if((unsigned)gy < 96u){
                asm volatile("st.shared.v2.b32 [%0],{%1,%1};"::"r"(dst),"r"(0):"memory");
                asm volatile("st.shared.v2.b32 [%0],{%1,%1};"::"r"(dst+392),"r"(0):"memory");
                asm volatile("st.shared.v2.b32 [%0],{%1,%1};"::"r"(dst+400),"r"(0):"memory");
                asm volatile("st.shared.v2.b32 [%0],{%1,%1};"::"r"(dst+408),"r"(0):"memory");
                const float* src = inB + ((size_t)(ch*16+kc)*HWD + gy)*HWD;
#pragma unroll
                for(int j=0;j<48;j++) CPA8(dst + 8 + j*8, src + j*2);
            } else {
#pragma unroll
                for(int j=0;j<26;j++)
                    asm volatile("st.shared.v4.b32 [%0],{%1,%1,%1,%1};"::"r"(dst+j*16),"r"(0):"memory");
            }
        }
        // ---- stage group 0 weights (taps 0..4) into buf 0 ----
        {
#pragma unroll
            for(int i=0;i<10;i++){
                int f4 = tid + i*128;
                int rec = f4>>5, l = f4&31;
                int tloc = rec>>3, r8 = rec&7;
                int kg2 = r8>>2, mb = r8&3;
                const float* gs = wrec + (((size_t)(tloc)*KG + ch*2 + kg2)*MBt + mb0 + mb)*128 + l*4;
                CPA16(wsmA + (uint32_t)(rec*512 + l*16), gs);
            }
        }
        CP_COMMIT(); CP_WAITG0();
        __syncthreads();

        for(int grp=0; grp<5; grp++){
            const int buf = grp&1;
            if(grp<4){
#pragma unroll
                for(int i=0;i<10;i++){
                    int f4 = tid + i*128;
                    int rec = f4>>5, l = f4&31;
                    int tloc = rec>>3, r8 = rec&7;
                    int kg2 = r8>>2, mb = r8&3;
                    const float* gs = wrec + (((size_t)((grp+1)*5 + tloc)*KG + ch*2 + kg2)*MBt + mb0 + mb)*128 + l*4;
                    CPA16(wsmA + (uint32_t)((1-buf)*20480 + rec*512 + l*16), gs);
                }
                CP_COMMIT();
            }
#pragma unroll
            for(int tloc=0; tloc<5; tloc++){
#pragma unroll
                for(int kg2=0; kg2<2; kg2++){
                    uint32_t A[4][4];
#pragma unroll
                    for(int m=0;m<4;m++){
                        const uint4 av = reinterpret_cast<const uint4*>(
                            wsm + buf*5120 + tloc*1024 + (kg2*4+m)*128)[lane];
                        A[m][0]=av.x; A[m][1]=av.y; A[m][2]=av.z; A[m][3]=av.w;
                    }
                    const float* ap = actm + (kg2*8 + (lane&3))*840 + (wy+grp)*104 + (lane>>2) + tloc;
#pragma unroll
                    for(int nb=0; nb<12; nb++){
                        uint32_t b0 = __float_as_uint(ap[nb*8]);
                        uint32_t b1 = __float_as_uint(ap[nb*8 + 3360]);
#pragma unroll
                        for(int m=0;m<4;m++) mma8(acc[m][nb], A[m], b0, b1);
                    }
                }
            }
            if(grp<4) CP_WAITG0();
            __syncthreads();
        }
    }

    // ---- epilogue (runtime act/rnd) ----
    const int act = S.actrnd & 15, rnd = S.actrnd >> 4;
    const int coutR = S.cout, oc0 = mb0*16;
#pragma unroll
    for(int m=0;m<4;m++){
        int ocm = oc0 + m*16 + (lane>>2);
#pragma unroll
        for(int h=0;h<2;h++){
            int oc = ocm + h*8;
            if(oc < coutR){
                float bv = S.bias[oc];
                float* row = S.outp + ((size_t)(b*coutR + oc)*HWD + (y0+wy))*HWD;
#pragma unroll
                for(int nb=0; nb<12; nb++){
                    float c0 = acc[m][nb][h*2+0] + bv;
                    float c1 = acc[m][nb][h*2+1] + bv;
                    if(act==1){ c0=fmaxf(c0,0.f); c1=fmaxf(c1,0.f); }
                    else if(act==2){ c0=(c0>=0.f)?c0:0.01f*c0; c1=(c1>=0.f)?c1:0.01f*c1; }
                    if(rnd){ c0=to_tf32(c0); c1=to_tf32(c1); }
                    *reinterpret_cast<float2*>(row + nb*8 + (lane&3)*2) = make_float2(c0,c1);
                }
            }
        }
    }
}

// ---------- global max ----------
__global__ void maxred_kernel(const float* __restrict__ x, float* __restrict__ gmax){
    __shared__ float sm[256];
    int bc=blockIdx.x;
    const float* p = x + (size_t)bc*HWD*HWD;
    float m=-3.402823466e38f;
    for(int i=threadIdx.x;i<HWD*HWD;i+=256) m=fmaxf(m,p[i]);
    sm[threadIdx.x]=m; __syncthreads();
    for(int st=128;st>0;st>>=1){ if(threadIdx.x<st) sm[threadIdx.x]=fmaxf(sm[threadIdx.x],sm[threadIdx.x+st]); __syncthreads(); }
    if(threadIdx.x==0) gmax[bc]=sm[0];
}

// ---------- lrelu -> 1x1 conv 576 -> grouped softmax ----------
__global__ void weights_kernel(const float* __restrict__ gmax, const float* __restrict__ ww3,
                               const float* __restrict__ bw3, float* __restrict__ outw){
    __shared__ float gsm[576]; __shared__ float osm[576];
    int b=blockIdx.x, t=threadIdx.x;
    float x=gmax[b*576+t];
    gsm[t]=(x>=0.f)?x:0.01f*x;
    __syncthreads();
    float a=bw3[t];
    const float* wr=ww3+(size_t)t*576;
    for(int i=0;i<576;i++) a=fmaf(wr[i],gsm[i],a);
    osm[t]=a; __syncthreads();
    if(t<192){
        float p=osm[t],q=osm[192+t],r=osm[384+t];
        float mx=fmaxf(p,fmaxf(q,r));
        float ep=expf(p-mx),eq=expf(q-mx),er=expf(r-mx);
        float inv=1.f/(ep+eq+er);
        outw[b*576+t]=ep*inv; outw[b*576+192+t]=eq*inv; outw[b*576+384+t]=er*inv;
    }
}

// ---------- launch ----------
static const int CONV_SMEM = 40960 + 16*840*4;   // 94720

extern "C" void kernel_launch(void* const* d_in, const int* in_sizes, int n_in, void* d_out, int out_size){
    const float* z2=(const float*)d_in[0];  const float* y1=(const float*)d_in[1];
    const float* ws1=(const float*)d_in[2]; const float* bs1=(const float*)d_in[3];
    const float* ws2=(const float*)d_in[4]; const float* bs2=(const float*)d_in[5];
    const float* ws3=(const float*)d_in[6]; const float* bs3=(const float*)d_in[7];
    const float* wm1=(const float*)d_in[8]; const float* bm1=(const float*)d_in[9];
    const float* wm2=(const float*)d_in[10];const float* bm2=(const float*)d_in[11];
    const float* wm3=(const float*)d_in[12];const float* bm3=(const float*)d_in[13];
    const float* ww1=(const float*)d_in[14];const float* bw1=(const float*)d_in[15];
    const float* ww2=(const float*)d_in[16];const float* bw2=(const float*)d_in[17];
    const float* ww3=(const float*)d_in[18];const float* bw3=(const float*)d_in[19];
    float* out=(float*)d_out;

    float *cat,*h1s,*h1m,*h1w,*h2s,*h2m,*ww2o,*gmax,*wtb;
    cudaGetSymbolAddress((void**)&cat,g_cat);
    cudaGetSymbolAddress((void**)&h1s,g_h1s);
    cudaGetSymbolAddress((void**)&h1m,g_h1m);
    cudaGetSymbolAddress((void**)&h1w,g_h1w);
    cudaGetSymbolAddress((void**)&h2s,g_h2s);
    cudaGetSymbolAddress((void**)&h2m,g_h2m);
    cudaGetSymbolAddress((void**)&ww2o,g_ww2);
    cudaGetSymbolAddress((void**)&gmax,g_gmax);
    cudaGetSymbolAddress((void**)&wtb,g_wt);

    cudaFuncSetAttribute(conv5_stage<320>, cudaFuncAttributeMaxDynamicSharedMemorySize, CONV_SMEM);
    cudaFuncSetAttribute(conv5_stage<128>, cudaFuncAttributeMaxDynamicSharedMemorySize, CONV_SMEM);

    const size_t MEA_OFF=(size_t)NB*576*HWD*HWD;
    const size_t WGT_OFF=2*MEA_OFF;

    const long O_S1=0, O_M1=1024000, O_W1=2048000, O_S2=3072000, O_M2=3481600,
               O_S3=3891200, O_M3=5734400, O_W2=7577600;
    {
        WT8 T;
        const float* ws[8] = {ws1,wm1,ww1,ws2,wm2,ws3,wm3,ww2};
        long offs[8]   = {O_S1,O_M1,O_W1,O_S2,O_M2,O_S3,O_M3,O_W2};
        int cins[8]    = {320,320,320,128,128,128,128,128};
        int couts[8]   = {128,128,128,128,128,576,576,576};
        long cum = 0;
        for(int i=0;i<8;i++){
            T.w[i]=ws[i]; T.off[i]=offs[i]; T.cin[i]=cins[i];
            T.KG[i]=cins[i]/8; T.MBt[i]=couts[i]/16;
            cum += 25L*T.KG[i]*T.MBt[i];
            T.recEnd[i]=cum;
        }
        long totalThr = cum*32;
        wtrans_all<<<(int)((totalThr+255)/256),256>>>(T, wtb, totalThr);
    }

    { long tot=(long)NB*320*HWD*HWD; upcat_kernel<<<(int)((tot+255)/256),256>>>(z2,y1,cat); }

    dim3 blk(128);
    auto mkslice=[](const float* in, float* outp, const float* wr, const float* bi,
                    int octile, int cout, int act, int rnd){
        ConvSlice s; s.in=in; s.outp=outp; s.wrec=wr; s.bias=bi;
        s.mb0=octile*4; s.MBt=cout/16; s.cout=cout; s.actrnd=act|(rnd<<4); return s;
    };

    // stage 1: s1,m1,w1 (CIN=320, cout=128) -> 6 slices
    {
        ConvTable T;
        int z=0;
        for(int ot=0; ot<2; ot++) T.s[z++]=mkslice(cat,h1s,wtb+O_S1,bs1,ot,128,1,1);
        for(int ot=0; ot<2; ot++) T.s[z++]=mkslice(cat,h1m,wtb+O_M1,bm1,ot,128,2,1);
        for(int ot=0; ot<2; ot++) T.s[z++]=mkslice(cat,h1w,wtb+O_W1,bw1,ot,128,2,1);
        conv5_stage<320><<<dim3(24,NB,6),blk,CONV_SMEM>>>(T);
    }
    // stage 2: s2,m2,ww2conv (CIN=128) -> 13 slices
    {
        ConvTable T;
        int z=0;
        for(int ot=0; ot<2; ot++) T.s[z++]=mkslice(h1s,h2s,wtb+O_S2,bs2,ot,128,1,1);
        for(int ot=0; ot<2; ot++) T.s[z++]=mkslice(h1m,h2m,wtb+O_M2,bm2,ot,128,2,1);
        for(int ot=0; ot<9; ot++) T.s[z++]=mkslice(h1w,ww2o,wtb+O_W2,bw2,ot,576,0,0);
        conv5_stage<128><<<dim3(24,NB,13),blk,CONV_SMEM>>>(T);
    }
    // maxred here (5th launch) so stage3 is the 6th -> ncu -s 5 -c 1 captures it
    maxred_kernel<<<NB*576,256>>>(ww2o,gmax);
    // stage 3: s3,m3 (CIN=128, cout=576) -> 18 slices
    {
        ConvTable T;
        int z=0;
        for(int ot=0; ot<9; ot++) T.s[z++]=mkslice(h2s,out,wtb+O_S3,bs3,ot,576,1,0);
        for(int ot=0; ot<9; ot++) T.s[z++]=mkslice(h2m,out+MEA_OFF,wtb+O_M3,bm3,ot,576,0,0);
        conv5_stage<128><<<dim3(24,NB,18),blk,CONV_SMEM>>>(T);
    }
    weights_kernel<<<NB,576>>>(gmax,ww3,bw3,out+WGT_OFF);
}